// round 14
// baseline (speedup 1.0000x reference)
#include <cuda_runtime.h>
#include <cuda_fp16.h>
#include <math.h>
#include <stdint.h>

#define BB 8
#define CC 512
#define TT 4096

static __device__ __align__(256) unsigned char g_scr[232u*1024u*1024u];

// ============================ helpers =======================================
__device__ __forceinline__ uint32_t smem_u32(const void* p){
    uint32_t a;
    asm("{ .reg .u64 t; cvta.to.shared.u64 t, %1; cvt.u32.u64 %0, t; }" : "=r"(a) : "l"(p));
    return a;
}
__device__ __forceinline__ void cpa16(uint32_t s, const void* g){
    asm volatile("cp.async.cg.shared.global [%0], [%1], 16;" :: "r"(s), "l"(g));
}
__device__ __forceinline__ void cpa_commit(){ asm volatile("cp.async.commit_group;" ::: "memory"); }
template<int N> __device__ __forceinline__ void cpa_wait(){
    asm volatile("cp.async.wait_group %0;" :: "n"(N) : "memory");
}
__device__ __forceinline__ void ldsm4(uint32_t* r, uint32_t addr){
    asm volatile("ldmatrix.sync.aligned.m8n8.x4.shared.b16 {%0,%1,%2,%3}, [%4];"
        : "=r"(r[0]), "=r"(r[1]), "=r"(r[2]), "=r"(r[3]) : "r"(addr));
}
__device__ __forceinline__ void ldsm4t(uint32_t* r, uint32_t addr){
    asm volatile("ldmatrix.sync.aligned.m8n8.x4.trans.shared.b16 {%0,%1,%2,%3}, [%4];"
        : "=r"(r[0]), "=r"(r[1]), "=r"(r[2]), "=r"(r[3]) : "r"(addr));
}
__device__ __forceinline__ void mma16816(float* d, const uint32_t* a, uint32_t b0, uint32_t b1){
    asm volatile("mma.sync.aligned.m16n8k16.row.col.f32.f16.f16.f32 "
        "{%0,%1,%2,%3}, {%4,%5,%6,%7}, {%8,%9}, {%0,%1,%2,%3};"
        : "+f"(d[0]), "+f"(d[1]), "+f"(d[2]), "+f"(d[3])
        : "r"(a[0]), "r"(a[1]), "r"(a[2]), "r"(a[3]), "r"(b0), "r"(b1));
}
__device__ __forceinline__ void split2h(float f, __half &h, __half &l){
    h = __float2half_rn(f);
    l = __float2half_rn(f - __half2float(h));
}
__device__ __forceinline__ float wred_sum(float v){
    #pragma unroll
    for(int o=16;o;o>>=1) v += __shfl_xor_sync(0xffffffffu, v, o);
    return v;
}
__device__ __forceinline__ float wred_max(float v){
    #pragma unroll
    for(int o=16;o;o>>=1) v = fmaxf(v, __shfl_xor_sync(0xffffffffu, v, o));
    return v;
}

// ============================================================================
// Split x elementwise: xh [b,c,t] (hi only); s[b,c] = rowsum
// ============================================================================
__global__ __launch_bounds__(256) void k_split_x(
    const float* __restrict__ x,
    __half* __restrict__ xh,
    float* __restrict__ s)
{
    __shared__ float wsum[8];
    const int c = blockIdx.x, b = blockIdx.y;
    const int tid = threadIdx.x;
    const size_t rb = ((size_t)b*CC + c)*TT;
    float sum = 0.f;
    #pragma unroll
    for(int it=0; it<4; it++){
        const int idx = (it*256 + tid)*4;
        float4 v = *(const float4*)(x + rb + idx);
        __align__(8) __half hv[4];
        hv[0]=__float2half_rn(v.x); hv[1]=__float2half_rn(v.y);
        hv[2]=__float2half_rn(v.z); hv[3]=__float2half_rn(v.w);
        *(uint2*)(xh + rb + idx) = *(uint2*)hv;
        sum += v.x + v.y + v.z + v.w;
    }
    sum = wred_sum(sum);
    if((tid&31)==0) wsum[tid>>5] = sum;
    __syncthreads();
    if(tid==0){
        float t = 0.f;
        #pragma unroll
        for(int i=0;i<8;i++) t += wsum[i];
        s[(size_t)b*CC + c] = t;
    }
}

__global__ __launch_bounds__(256) void k_split_w(
    const float* __restrict__ Wq, const float* __restrict__ Wk,
    __half* __restrict__ qh, __half* __restrict__ ql,
    __half* __restrict__ kh, __half* __restrict__ kl)
{
    const int which = blockIdx.y;
    const float* W = which ? Wk : Wq;
    __half* oh = which ? kh : qh;
    __half* ol = which ? kl : ql;
    size_t i = ((size_t)blockIdx.x*256 + threadIdx.x)*4;
    float4 v = *(const float4*)(W + i);
    __align__(8) __half hv[4], lv[4];
    split2h(v.x,hv[0],lv[0]); split2h(v.y,hv[1],lv[1]);
    split2h(v.z,hv[2],lv[2]); split2h(v.w,hv[3],lv[3]);
    *(uint2*)(oh+i) = *(uint2*)hv;
    *(uint2*)(ol+i) = *(uint2*)lv;
}

// transpose Wv -> WvT hi only
__global__ __launch_bounds__(256) void k_split_wT(
    const float* __restrict__ Wv, __half* __restrict__ th)
{
    __shared__ float tile[32][129];
    const int o0 = blockIdx.x*128, d0 = blockIdx.y*32;
    const int tx = threadIdx.x & 31, ty = threadIdx.x >> 5;
    #pragma unroll
    for(int i=0;i<4;i++){
        const int dl = ty + 8*i;
        float4 v = *(const float4*)(Wv + (size_t)(d0+dl)*CC + o0 + tx*4);
        tile[dl][tx*4+0]=v.x; tile[dl][tx*4+1]=v.y;
        tile[dl][tx*4+2]=v.z; tile[dl][tx*4+3]=v.w;
    }
    __syncthreads();
    const int r = threadIdx.x>>1, h = threadIdx.x&1;
    __align__(16) __half hv[16];
    #pragma unroll
    for(int j=0;j<16;j++) hv[j] = __float2half_rn(tile[h*16+j][r]);
    size_t ob = (size_t)(o0 + r)*CC + d0 + h*16;
    *(uint4*)(th+ob)   = *(uint4*)hv;  *(uint4*)(th+ob+8) = *(uint4*)(hv+8);
}

__global__ __launch_bounds__(256) void k_uw(
    const float* __restrict__ Wq, const float* __restrict__ Wk,
    const float* __restrict__ s, float* __restrict__ u, float* __restrict__ w)
{
    const int b = blockIdx.z;
    const int which = blockIdx.y;
    const float* __restrict__ W = which ? Wk : Wq;
    const int o = blockIdx.x*8 + (threadIdx.x>>5);
    const int lane = threadIdx.x & 31;
    const float* __restrict__ sp = s + (size_t)b*CC;
    float acc = 0.f;
    #pragma unroll
    for(int it=0; it<4; it++){
        int c = lane*4 + it*128;
        float4 wv = *(const float4*)(W + (size_t)o*CC + c);
        float4 sv = *(const float4*)(sp + c);
        acc += wv.x*sv.x + wv.y*sv.y + wv.z*sv.z + wv.w*sv.w;
    }
    acc = wred_sum(acc);
    if(lane==0) (which ? w : u)[(size_t)b*CC + o] = acc;
}

// row softmax over 512; attn -> ah (fp16 hi only); r = attn . bv
__global__ __launch_bounds__(256) void k_softmax(
    const float* __restrict__ dots,
    __half* __restrict__ ah,
    const float* __restrict__ bv, float* __restrict__ r)
{
    const int b = blockIdx.y;
    const int row = blockIdx.x*8 + (threadIdx.x>>5);
    const int lane = threadIdx.x & 31;
    const float* __restrict__ dr = dots + ((size_t)b*CC + row)*CC;
    float v[16];
    float mx = -1e30f;
    #pragma unroll
    for(int it=0; it<4; it++){
        float4 t = *(const float4*)(dr + lane*4 + it*128);
        v[it*4+0]=t.x; v[it*4+1]=t.y; v[it*4+2]=t.z; v[it*4+3]=t.w;
        mx = fmaxf(mx, fmaxf(fmaxf(t.x,t.y), fmaxf(t.z,t.w)));
    }
    mx = wred_max(mx);
    float sum = 0.f;
    #pragma unroll
    for(int j=0;j<16;j++){ v[j] = expf(v[j]-mx); sum += v[j]; }
    sum = wred_sum(sum);
    const float inv = 1.f/sum;
    float rd = 0.f;
    size_t rb = ((size_t)b*CC + row)*CC;
    #pragma unroll
    for(int it=0; it<4; it++){
        float4 bv4 = *(const float4*)(bv + lane*4 + it*128);
        float a0=v[it*4+0]*inv, a1=v[it*4+1]*inv, a2=v[it*4+2]*inv, a3=v[it*4+3]*inv;
        rd += a0*bv4.x + a1*bv4.y + a2*bv4.z + a3*bv4.w;
        __align__(8) __half hv[4];
        hv[0]=__float2half_rn(a0); hv[1]=__float2half_rn(a1);
        hv[2]=__float2half_rn(a2); hv[3]=__float2half_rn(a3);
        *(uint2*)(ah + rb + lane*4 + it*128) = *(uint2*)hv;
    }
    rd = wred_sum(rd);
    if(lane==0) r[(size_t)b*CC + row] = rd;
}

// ============================================================================
// fp16 split GEMM: BM=BN=128, BK=KB (32 or 64), 8 warps of 64x32, 2-stage.
// NPROD=1: ah*bh. NPROD=2: +ah*bl. NPROD=3: +al*bh.
// MODE 0: split fp16 hi/lo; 1: dots; 2: +r fp32; 3: fp32 partial (SYM);
// MODE 4: fp16 hi only.
// LAYB=0 NT; LAYB=1 NN (272B rows, ldmatrix.trans).
// SMEM layout (compact): A@0, [A-lo@TILE if NPROD==3], Bh@BHO, [Bl@BHO+BT]
// ============================================================================
#define BROW_NN 272

template<int MODE, int NPROD, int SYM, int LAYB, int KB>
__global__ __launch_bounds__(256,2) void k_wmma_nt(
    const __half* __restrict__ Ah, const __half* __restrict__ Al, size_t strA,
    const __half* __restrict__ Bh, const __half* __restrict__ Bl, size_t strB,
    int K, int ldka, int ldkb,
    void* out1, void* out2, size_t strO, int ldo,
    const float* __restrict__ vu, const float* __restrict__ vw,
    const float* __restrict__ vbq, const float* __restrict__ vbk,
    const float* __restrict__ vr)
{
    constexpr int ROWB = KB*2 + 16;
    constexpr int TILE = 128*ROWB;
    constexpr int BT_NN = KB*BROW_NN;
    constexpr int BHO = (NPROD==3) ? 2*TILE : TILE;
    constexpr int BT = (LAYB==0) ? TILE : BT_NN;
    constexpr int STG = BHO + ((NPROD>=2) ? 2 : 1)*BT;
    constexpr int NCPA = KB/16;      // 16B copies per thread per tile
    constexpr int NKS  = KB/16;      // k16 steps per chunk

    extern __shared__ __align__(128) unsigned char smem[];
    const uint32_t sb = smem_u32(smem);
    const int tid = threadIdx.x, lane = tid&31, wid = tid>>5;
    const int b = blockIdx.z;
    int m0, n0; size_t koff;
    if(SYM){
        const int t = blockIdx.x;
        const int ti = t<4?0 : (t<7?1 : (t<9?2:3));
        const int tj = t - (ti==0?0 : (ti==1?3 : (ti==2?5:6)));
        m0 = ti*128; n0 = tj*128;
        koff = (size_t)blockIdx.y * K;
    } else {
        m0 = blockIdx.y*128; n0 = blockIdx.x*128; koff = 0;
    }

    const int r = tid>>1, h = tid&1;
    const __half* gA0 = Ah + strA*b + (size_t)(m0+r)*ldka + koff + h*(KB/2);
    const __half* gA1 = (NPROD==3) ? (Al + strA*b + (size_t)(m0+r)*ldka + koff + h*(KB/2)) : nullptr;
    const __half* gB0;
    const __half* gB1 = nullptr;
    uint32_t sdstB;
    if(LAYB==0){
        gB0 = Bh + strB*b + (size_t)(n0+r)*ldkb + koff + h*(KB/2);
        if(NPROD>=2) gB1 = Bl + strB*b + (size_t)(n0+r)*ldkb + koff + h*(KB/2);
        sdstB = sb + BHO + (uint32_t)(r*ROWB + h*KB);
    } else {
        constexpr int TPR = 256/KB;          // threads per B row
        const int kr = tid/TPR, cg = tid%TPR;
        gB0 = Bh + strB*b + (size_t)kr*ldkb + n0 + cg*(KB/2);
        if(NPROD>=2) gB1 = Bl + strB*b + (size_t)kr*ldkb + n0 + cg*(KB/2);
        sdstB = sb + BHO + (uint32_t)(kr*BROW_NN + cg*KB);
    }
    const uint32_t sdstA = sb + (uint32_t)(r*ROWB + h*KB);

    auto load_chunk = [&](int c){
        const uint32_t so = (uint32_t)(c&1)*STG;
        const size_t koA = (size_t)c*KB;
        #pragma unroll
        for(int j=0;j<NCPA;j++) cpa16(sdstA+so+j*16, gA0+koA+j*8);
        if(NPROD==3){
            #pragma unroll
            for(int j=0;j<NCPA;j++) cpa16(sdstA+so+TILE+j*16, gA1+koA+j*8);
        }
        if(LAYB==0){
            #pragma unroll
            for(int j=0;j<NCPA;j++) cpa16(sdstB+so+j*16, gB0+koA+j*8);
            if(NPROD>=2){
                #pragma unroll
                for(int j=0;j<NCPA;j++) cpa16(sdstB+so+BT+j*16, gB1+koA+j*8);
            }
        } else {
            const size_t koB = (size_t)c*KB*ldkb;
            #pragma unroll
            for(int j=0;j<NCPA;j++) cpa16(sdstB+so+j*16, gB0+koB+j*8);
            if(NPROD>=2){
                #pragma unroll
                for(int j=0;j<NCPA;j++) cpa16(sdstB+so+BT+j*16, gB1+koB+j*8);
            }
        }
        cpa_commit();
    };
    load_chunk(0);

    const int wm = wid&1, wn = wid>>1;
    const int lr16 = lane&15, lkc = lane>>4;
    float acc[4][4][4];
    #pragma unroll
    for(int i=0;i<4;i++)
        #pragma unroll
        for(int j=0;j<4;j++){ acc[i][j][0]=0.f; acc[i][j][1]=0.f; acc[i][j][2]=0.f; acc[i][j][3]=0.f; }

    const int nch = K/KB;
    for(int c=0;c<nch;c++){
        if(c+1 < nch){ load_chunk(c+1); cpa_wait<1>(); }
        else         { cpa_wait<0>(); }
        __syncthreads();
        const uint32_t sbase = sb + (uint32_t)(c&1)*STG;
        #pragma unroll
        for(int ks=0; ks<NKS; ks++){
            const uint32_t coff = (uint32_t)((ks*2 + lkc)*16);
            uint32_t ahf[4][4], bhf[2][4], blf[2][4];
            #pragma unroll
            for(int mt=0; mt<4; mt++){
                const uint32_t a = sbase + (uint32_t)((wm*64 + mt*16 + lr16)*ROWB) + coff;
                ldsm4(ahf[mt], a);
            }
            if(LAYB==0){
                #pragma unroll
                for(int g=0; g<2; g++){
                    const uint32_t a = sbase + BHO + (uint32_t)((wn*32 + g*16 + lr16)*ROWB) + coff;
                    ldsm4(bhf[g], a);
                    if(NPROD>=2) ldsm4(blf[g], a + BT);
                }
            } else {
                #pragma unroll
                for(int g=0; g<2; g++){
                    const uint32_t a = sbase + BHO
                        + (uint32_t)((ks*16 + lr16)*BROW_NN)
                        + (uint32_t)((wn*32 + g*16 + lkc*8)*2);
                    ldsm4t(bhf[g], a);
                    if(NPROD>=2) ldsm4t(blf[g], a + BT);
                }
            }
            #pragma unroll
            for(int mt=0; mt<4; mt++)
                #pragma unroll
                for(int nt=0; nt<4; nt++){
                    const int g = nt>>1, p = nt&1;
                    const uint32_t h0 = LAYB ? bhf[g][p*2]   : bhf[g][p];
                    const uint32_t h1 = LAYB ? bhf[g][p*2+1] : bhf[g][p+2];
                    mma16816(acc[mt][nt], ahf[mt], h0, h1);
                    if(NPROD>=2){
                        const uint32_t l0 = LAYB ? blf[g][p*2]   : blf[g][p];
                        const uint32_t l1 = LAYB ? blf[g][p*2+1] : blf[g][p+2];
                        mma16816(acc[mt][nt], ahf[mt], l0, l1);
                    }
                }
            if(NPROD==3){
                uint32_t alf[4][4];
                #pragma unroll
                for(int mt=0; mt<4; mt++){
                    const uint32_t a = sbase + TILE + (uint32_t)((wm*64 + mt*16 + lr16)*ROWB) + coff;
                    ldsm4(alf[mt], a);
                }
                #pragma unroll
                for(int mt=0; mt<4; mt++)
                    #pragma unroll
                    for(int nt=0; nt<4; nt++){
                        const int g = nt>>1, p = nt&1;
                        const uint32_t h0 = LAYB ? bhf[g][p*2]   : bhf[g][p];
                        const uint32_t h1 = LAYB ? bhf[g][p*2+1] : bhf[g][p+2];
                        mma16816(acc[mt][nt], alf[mt], h0, h1);
                    }
            }
        }
        __syncthreads();
    }

    const int er = lane>>2, ec = (lane&3)*2;
    if(MODE == 3){
        float* oF = (float*)out1
            + ((size_t)(blockIdx.y*10u + blockIdx.x)*gridDim.z + b)*16384u;
        #pragma unroll
        for(int mt=0; mt<4; mt++){
            const int m = wm*64 + mt*16 + er;
            #pragma unroll
            for(int nt=0; nt<4; nt++){
                const int n = wn*32 + nt*8 + ec;
                const float* d = acc[mt][nt];
                *(float2*)(oF + (size_t)m*128 + n)     = make_float2(d[0], d[1]);
                *(float2*)(oF + (size_t)(m+8)*128 + n) = make_float2(d[2], d[3]);
            }
        }
        return;
    }
    const int mW = m0 + wm*64, nW = n0 + wn*32;
    if(MODE == 0){
        __half* oH = (__half*)out1 + strO*b;
        __half* oL = (__half*)out2 + strO*b;
        #pragma unroll
        for(int mt=0; mt<4; mt++){
            const int m = mW + mt*16 + er;
            #pragma unroll
            for(int nt=0; nt<4; nt++){
                const int n = nW + nt*8 + ec;
                const float* d = acc[mt][nt];
                __half h0,l0,h1,l1;
                split2h(d[0],h0,l0); split2h(d[1],h1,l1);
                *(__half2*)(oH + (size_t)m*ldo + n) = __halves2half2(h0,h1);
                *(__half2*)(oL + (size_t)m*ldo + n) = __halves2half2(l0,l1);
                split2h(d[2],h0,l0); split2h(d[3],h1,l1);
                *(__half2*)(oH + (size_t)(m+8)*ldo + n) = __halves2half2(h0,h1);
                *(__half2*)(oL + (size_t)(m+8)*ldo + n) = __halves2half2(l0,l1);
            }
        }
    } else if(MODE == 4){
        __half* oH = (__half*)out1 + strO*b;
        #pragma unroll
        for(int mt=0; mt<4; mt++){
            const int m = mW + mt*16 + er;
            #pragma unroll
            for(int nt=0; nt<4; nt++){
                const int n = nW + nt*8 + ec;
                const float* d = acc[mt][nt];
                *(__half2*)(oH + (size_t)m*ldo + n) =
                    __halves2half2(__float2half_rn(d[0]), __float2half_rn(d[1]));
                *(__half2*)(oH + (size_t)(m+8)*ldo + n) =
                    __halves2half2(__float2half_rn(d[2]), __float2half_rn(d[3]));
            }
        }
    } else if(MODE == 1){
        float* oF = (float*)out1 + strO*b;
        #pragma unroll
        for(int mt=0; mt<4; mt++){
            const int m = mW + mt*16 + er;
            const float u0 = vu[(size_t)b*CC + m],   u1 = vu[(size_t)b*CC + m + 8];
            const float q0 = vbq[m],                 q1 = vbq[m + 8];
            #pragma unroll
            for(int nt=0; nt<4; nt++){
                const int n = nW + nt*8 + ec;
                const float2 bk2 = *(const float2*)(vbk + n);
                const float2 w2  = *(const float2*)(vw + (size_t)b*CC + n);
                const float t0 = w2.x + 4096.0f*bk2.x, t1 = w2.y + 4096.0f*bk2.y;
                const float* d = acc[mt][nt];
                float2 o0, o1;
                o0.x = (d[0] + u0*bk2.x + q0*t0)*0.125f;
                o0.y = (d[1] + u0*bk2.y + q0*t1)*0.125f;
                o1.x = (d[2] + u1*bk2.x + q1*t0)*0.125f;
                o1.y = (d[3] + u1*bk2.y + q1*t1)*0.125f;
                *(float2*)(oF + (size_t)m*ldo + n)     = o0;
                *(float2*)(oF + (size_t)(m+8)*ldo + n) = o1;
            }
        }
    } else {
        float* oF = (float*)out1 + strO*b;
        #pragma unroll
        for(int mt=0; mt<4; mt++){
            const int m = mW + mt*16 + er;
            const float r0 = vr[(size_t)b*CC + m], r1 = vr[(size_t)b*CC + m + 8];
            #pragma unroll
            for(int nt=0; nt<4; nt++){
                const int n = nW + nt*8 + ec;
                const float* d = acc[mt][nt];
                *(float2*)(oF + (size_t)m*ldo + n)     = make_float2(d[0]+r0, d[1]+r0);
                *(float2*)(oF + (size_t)(m+8)*ldo + n) = make_float2(d[2]+r1, d[3]+r1);
            }
        }
    }
}

// ============================================================================
// G reduce: sum 2 K-slice partials, split fp16 hi/lo, write tile + mirror.
// ============================================================================
__global__ __launch_bounds__(256) void k_gsum(
    const float* __restrict__ P, __half* __restrict__ Gh, __half* __restrict__ Gl)
{
    extern __shared__ float sm[];
    const int t = blockIdx.x, b = blockIdx.y;
    const int ti = t<4?0 : (t<7?1 : (t<9?2:3));
    const int tj = t - (ti==0?0 : (ti==1?3 : (ti==2?5:6)));
    const int tid = threadIdx.x;
    const float4* p4 = (const float4*)P;
    #pragma unroll
    for(int v=0; v<16; v++){
        const int f4 = v*256 + tid;
        float4 a = make_float4(0.f,0.f,0.f,0.f);
        #pragma unroll
        for(int s=0;s<2;s++){
            float4 q = p4[(size_t)((s*10 + t)*BB + b)*4096u + f4];
            a.x+=q.x; a.y+=q.y; a.z+=q.z; a.w+=q.w;
        }
        const int e = f4*4, m = e>>7, n = e&127;
        sm[m*129+n]=a.x; sm[m*129+n+1]=a.y; sm[m*129+n+2]=a.z; sm[m*129+n+3]=a.w;
    }
    __syncthreads();
    const int M0 = ti*128, N0 = tj*128;
    __half* GhB = Gh + (size_t)b*CC*CC;
    __half* GlB = Gl + (size_t)b*CC*CC;
    #pragma unroll
    for(int v=0; v<32; v++){
        const int h2 = v*256 + tid;
        const int m = h2>>6, n2 = h2&63;
        __half h0,l0,h1,l1;
        split2h(sm[m*129 + 2*n2],     h0,l0);
        split2h(sm[m*129 + 2*n2 + 1], h1,l1);
        const size_t o = (size_t)(M0+m)*CC + N0 + 2*n2;
        *(__half2*)(GhB+o) = __halves2half2(h0,h1);
        *(__half2*)(GlB+o) = __halves2half2(l0,l1);
    }
    if(ti != tj){
        #pragma unroll
        for(int v=0; v<32; v++){
            const int h2 = v*256 + tid;
            const int mr = h2>>6, c2 = h2&63;
            __half h0,l0,h1,l1;
            split2h(sm[(2*c2)*129 + mr],   h0,l0);
            split2h(sm[(2*c2+1)*129 + mr], h1,l1);
            const size_t o = (size_t)(N0+mr)*CC + M0 + 2*c2;
            *(__half2*)(GhB+o) = __halves2half2(h0,h1);
            *(__half2*)(GlB+o) = __halves2half2(l0,l1);
        }
    }
}

// ============================================================================
extern "C" void kernel_launch(void* const* d_in, const int* in_sizes, int n_in,
                              void* d_out, int out_size)
{
    const float* x  = (const float*)d_in[0];
    const float* Wq = (const float*)d_in[1];
    const float* bq = (const float*)d_in[2];
    const float* Wk = (const float*)d_in[3];
    const float* bk = (const float*)d_in[4];
    const float* Wv = (const float*)d_in[5];
    const float* bv = (const float*)d_in[6];
    float* out = (float*)d_out;

    void* basep = nullptr;
    cudaGetSymbolAddress(&basep, g_scr);
    unsigned char* base = (unsigned char*)basep;

    const size_t XE = (size_t)BB*CC*TT;
    const size_t WE = (size_t)CC*CC;
    const size_t GE = (size_t)BB*CC*CC;
    size_t off = 0;
    auto take = [&](size_t bytes){ size_t o = off; off += (bytes + 255) & ~(size_t)255; return o; };
    __half* xh  = (__half*)(base + take(XE*2));
    __half* wqh = (__half*)(base + take(WE*2));
    __half* wql = (__half*)(base + take(WE*2));
    __half* wkh = (__half*)(base + take(WE*2));
    __half* wkl = (__half*)(base + take(WE*2));
    __half* wvth= (__half*)(base + take(WE*2));
    __half* Gh  = (__half*)(base + take(GE*2));
    __half* Gl  = (__half*)(base + take(GE*2));
    __half* Hh  = (__half*)(base + take(GE*2));
    __half* Hl  = (__half*)(base + take(GE*2));
    __half* Mh  = (__half*)(base + take(GE*2));
    __half* ah  = (__half*)(base + take(GE*2));
    float* dots = (float*)(base + take(GE*4));
    float* Gpart= (float*)(base + take((size_t)2*10*BB*16384*4));
    float* s    = (float*)(base + take((size_t)BB*CC*4));
    float* u    = (float*)(base + take((size_t)BB*CC*4));
    float* w    = (float*)(base + take((size_t)BB*CC*4));
    float* rr   = (float*)(base + take((size_t)BB*CC*4));

    // smem sizes: H/dots (NPROD=3,KB=32): 81920; M (NPROD=1,KB=32): 40960
    // G (NPROD=1,NT,KB=64): 73728; out (NPROD=1,NN,KB=64): 71680
    cudaFuncSetAttribute(k_wmma_nt<0,3,0,0,32>, cudaFuncAttributeMaxDynamicSharedMemorySize, 81920);
    cudaFuncSetAttribute(k_wmma_nt<1,3,0,0,32>, cudaFuncAttributeMaxDynamicSharedMemorySize, 81920);
    cudaFuncSetAttribute(k_wmma_nt<4,1,0,0,32>, cudaFuncAttributeMaxDynamicSharedMemorySize, 40960);
    cudaFuncSetAttribute(k_wmma_nt<2,1,0,1,64>, cudaFuncAttributeMaxDynamicSharedMemorySize, 71680);
    cudaFuncSetAttribute(k_wmma_nt<3,1,1,0,64>, cudaFuncAttributeMaxDynamicSharedMemorySize, 73728);
    cudaFuncSetAttribute(k_gsum, cudaFuncAttributeMaxDynamicSharedMemorySize, 66048);

    dim3 blk(256,1,1);
    k_split_x<<<dim3(CC, BB), blk>>>(x, xh, s);
    k_split_w<<<dim3(CC*CC/1024, 2, 1), blk>>>(Wq, Wk, wqh, wql, wkh, wkl);
    k_split_wT<<<dim3(CC/128, CC/32, 1), blk>>>(Wv, wvth);
    k_uw<<<dim3(CC/8, 2, BB), blk>>>(Wq, Wk, s, u, w);
    // G partials: upper tiles, NPROD=1 (xh*xh^T), split-K x2, BK=64
    k_wmma_nt<3,1,1,0,64><<<dim3(10, 2, BB), blk, 73728>>>(
        xh, nullptr, (size_t)CC*TT, xh, nullptr, (size_t)CC*TT, 2048, TT, TT,
        Gpart, nullptr, 0, 128, nullptr,nullptr,nullptr,nullptr,nullptr);
    k_gsum<<<dim3(10, BB), blk, 66048>>>(Gpart, Gh, Gl);
    // H = Wq G (G symmetric -> NT; 3 products) -> Hh,Hl
    k_wmma_nt<0,3,0,0,32><<<dim3(CC/128, CC/128, BB), blk, 81920>>>(
        wqh, wql, (size_t)0, Gh, Gl, (size_t)CC*CC, CC, CC, CC,
        Hh, Hl, (size_t)CC*CC, CC, nullptr,nullptr,nullptr,nullptr,nullptr);
    // dots = H Wk^T + rank-1, scaled (3 products)
    k_wmma_nt<1,3,0,0,32><<<dim3(CC/128, CC/128, BB), blk, 81920>>>(
        Hh, Hl, (size_t)CC*CC, wkh, wkl, (size_t)0, CC, CC, CC,
        dots, nullptr, (size_t)CC*CC, CC, u, w, bq, bk, nullptr);
    // softmax -> ah ; r = attn.bv
    k_softmax<<<dim3(CC/8, BB), blk>>>(dots, ah, bv, rr);
    // M = ah WvT^T (1 product), fp16-hi out
    k_wmma_nt<4,1,0,0,32><<<dim3(CC/128, CC/128, BB), blk, 40960>>>(
        ah, nullptr, (size_t)CC*CC, wvth, nullptr, (size_t)0, CC, CC, CC,
        Mh, nullptr, (size_t)CC*CC, CC, nullptr,nullptr,nullptr,nullptr,nullptr);
    // out = Mh xh + r  (NN, single product, BK=64)
    k_wmma_nt<2,1,0,1,64><<<dim3(TT/128, CC/128, BB), blk, 71680>>>(
        Mh, nullptr, (size_t)CC*CC, xh, nullptr, (size_t)CC*TT, 512, CC, TT,
        out, nullptr, (size_t)CC*TT, TT, nullptr,nullptr,nullptr,nullptr, rr);
}

// round 15
// speedup vs baseline: 1.0708x; 1.0708x over previous
#include <cuda_runtime.h>
#include <cuda_fp16.h>
#include <math.h>
#include <stdint.h>

#define BB 8
#define CC 512
#define TT 4096

static __device__ __align__(256) unsigned char g_scr[232u*1024u*1024u];

// ============================ helpers =======================================
__device__ __forceinline__ uint32_t smem_u32(const void* p){
    uint32_t a;
    asm("{ .reg .u64 t; cvta.to.shared.u64 t, %1; cvt.u32.u64 %0, t; }" : "=r"(a) : "l"(p));
    return a;
}
__device__ __forceinline__ void cpa16(uint32_t s, const void* g){
    asm volatile("cp.async.cg.shared.global [%0], [%1], 16;" :: "r"(s), "l"(g));
}
__device__ __forceinline__ void cpa_commit(){ asm volatile("cp.async.commit_group;" ::: "memory"); }
template<int N> __device__ __forceinline__ void cpa_wait(){
    asm volatile("cp.async.wait_group %0;" :: "n"(N) : "memory");
}
__device__ __forceinline__ void ldsm4(uint32_t* r, uint32_t addr){
    asm volatile("ldmatrix.sync.aligned.m8n8.x4.shared.b16 {%0,%1,%2,%3}, [%4];"
        : "=r"(r[0]), "=r"(r[1]), "=r"(r[2]), "=r"(r[3]) : "r"(addr));
}
__device__ __forceinline__ void ldsm4t(uint32_t* r, uint32_t addr){
    asm volatile("ldmatrix.sync.aligned.m8n8.x4.trans.shared.b16 {%0,%1,%2,%3}, [%4];"
        : "=r"(r[0]), "=r"(r[1]), "=r"(r[2]), "=r"(r[3]) : "r"(addr));
}
__device__ __forceinline__ void mma16816(float* d, const uint32_t* a, uint32_t b0, uint32_t b1){
    asm volatile("mma.sync.aligned.m16n8k16.row.col.f32.f16.f16.f32 "
        "{%0,%1,%2,%3}, {%4,%5,%6,%7}, {%8,%9}, {%0,%1,%2,%3};"
        : "+f"(d[0]), "+f"(d[1]), "+f"(d[2]), "+f"(d[3])
        : "r"(a[0]), "r"(a[1]), "r"(a[2]), "r"(a[3]), "r"(b0), "r"(b1));
}
__device__ __forceinline__ void split2h(float f, __half &h, __half &l){
    h = __float2half_rn(f);
    l = __float2half_rn(f - __half2float(h));
}
__device__ __forceinline__ float wred_sum(float v){
    #pragma unroll
    for(int o=16;o;o>>=1) v += __shfl_xor_sync(0xffffffffu, v, o);
    return v;
}
__device__ __forceinline__ float wred_max(float v){
    #pragma unroll
    for(int o=16;o;o>>=1) v = fmaxf(v, __shfl_xor_sync(0xffffffffu, v, o));
    return v;
}

// ============================================================================
// Split x elementwise: xh [b,c,t] (hi only); s[b,c] = rowsum
// ============================================================================
__global__ __launch_bounds__(256) void k_split_x(
    const float* __restrict__ x,
    __half* __restrict__ xh,
    float* __restrict__ s)
{
    __shared__ float wsum[8];
    const int c = blockIdx.x, b = blockIdx.y;
    const int tid = threadIdx.x;
    const size_t rb = ((size_t)b*CC + c)*TT;
    float sum = 0.f;
    #pragma unroll
    for(int it=0; it<4; it++){
        const int idx = (it*256 + tid)*4;
        float4 v = *(const float4*)(x + rb + idx);
        __align__(8) __half hv[4];
        hv[0]=__float2half_rn(v.x); hv[1]=__float2half_rn(v.y);
        hv[2]=__float2half_rn(v.z); hv[3]=__float2half_rn(v.w);
        *(uint2*)(xh + rb + idx) = *(uint2*)hv;
        sum += v.x + v.y + v.z + v.w;
    }
    sum = wred_sum(sum);
    if((tid&31)==0) wsum[tid>>5] = sum;
    __syncthreads();
    if(tid==0){
        float t = 0.f;
        #pragma unroll
        for(int i=0;i<8;i++) t += wsum[i];
        s[(size_t)b*CC + c] = t;
    }
}

__global__ __launch_bounds__(256) void k_split_w(
    const float* __restrict__ Wq, const float* __restrict__ Wk,
    __half* __restrict__ qh, __half* __restrict__ ql,
    __half* __restrict__ kh, __half* __restrict__ kl)
{
    const int which = blockIdx.y;
    const float* W = which ? Wk : Wq;
    __half* oh = which ? kh : qh;
    __half* ol = which ? kl : ql;
    size_t i = ((size_t)blockIdx.x*256 + threadIdx.x)*4;
    float4 v = *(const float4*)(W + i);
    __align__(8) __half hv[4], lv[4];
    split2h(v.x,hv[0],lv[0]); split2h(v.y,hv[1],lv[1]);
    split2h(v.z,hv[2],lv[2]); split2h(v.w,hv[3],lv[3]);
    *(uint2*)(oh+i) = *(uint2*)hv;
    *(uint2*)(ol+i) = *(uint2*)lv;
}

// transpose Wv -> WvT hi only
__global__ __launch_bounds__(256) void k_split_wT(
    const float* __restrict__ Wv, __half* __restrict__ th)
{
    __shared__ float tile[32][129];
    const int o0 = blockIdx.x*128, d0 = blockIdx.y*32;
    const int tx = threadIdx.x & 31, ty = threadIdx.x >> 5;
    #pragma unroll
    for(int i=0;i<4;i++){
        const int dl = ty + 8*i;
        float4 v = *(const float4*)(Wv + (size_t)(d0+dl)*CC + o0 + tx*4);
        tile[dl][tx*4+0]=v.x; tile[dl][tx*4+1]=v.y;
        tile[dl][tx*4+2]=v.z; tile[dl][tx*4+3]=v.w;
    }
    __syncthreads();
    const int r = threadIdx.x>>1, h = threadIdx.x&1;
    __align__(16) __half hv[16];
    #pragma unroll
    for(int j=0;j<16;j++) hv[j] = __float2half_rn(tile[h*16+j][r]);
    size_t ob = (size_t)(o0 + r)*CC + d0 + h*16;
    *(uint4*)(th+ob)   = *(uint4*)hv;  *(uint4*)(th+ob+8) = *(uint4*)(hv+8);
}

__global__ __launch_bounds__(256) void k_uw(
    const float* __restrict__ Wq, const float* __restrict__ Wk,
    const float* __restrict__ s, float* __restrict__ u, float* __restrict__ w)
{
    const int b = blockIdx.z;
    const int which = blockIdx.y;
    const float* __restrict__ W = which ? Wk : Wq;
    const int o = blockIdx.x*8 + (threadIdx.x>>5);
    const int lane = threadIdx.x & 31;
    const float* __restrict__ sp = s + (size_t)b*CC;
    float acc = 0.f;
    #pragma unroll
    for(int it=0; it<4; it++){
        int c = lane*4 + it*128;
        float4 wv = *(const float4*)(W + (size_t)o*CC + c);
        float4 sv = *(const float4*)(sp + c);
        acc += wv.x*sv.x + wv.y*sv.y + wv.z*sv.z + wv.w*sv.w;
    }
    acc = wred_sum(acc);
    if(lane==0) (which ? w : u)[(size_t)b*CC + o] = acc;
}

// row softmax over 512; attn -> ah (fp16 hi only); r = attn . bv
__global__ __launch_bounds__(256) void k_softmax(
    const float* __restrict__ dots,
    __half* __restrict__ ah,
    const float* __restrict__ bv, float* __restrict__ r)
{
    const int b = blockIdx.y;
    const int row = blockIdx.x*8 + (threadIdx.x>>5);
    const int lane = threadIdx.x & 31;
    const float* __restrict__ dr = dots + ((size_t)b*CC + row)*CC;
    float v[16];
    float mx = -1e30f;
    #pragma unroll
    for(int it=0; it<4; it++){
        float4 t = *(const float4*)(dr + lane*4 + it*128);
        v[it*4+0]=t.x; v[it*4+1]=t.y; v[it*4+2]=t.z; v[it*4+3]=t.w;
        mx = fmaxf(mx, fmaxf(fmaxf(t.x,t.y), fmaxf(t.z,t.w)));
    }
    mx = wred_max(mx);
    float sum = 0.f;
    #pragma unroll
    for(int j=0;j<16;j++){ v[j] = expf(v[j]-mx); sum += v[j]; }
    sum = wred_sum(sum);
    const float inv = 1.f/sum;
    float rd = 0.f;
    size_t rb = ((size_t)b*CC + row)*CC;
    #pragma unroll
    for(int it=0; it<4; it++){
        float4 bv4 = *(const float4*)(bv + lane*4 + it*128);
        float a0=v[it*4+0]*inv, a1=v[it*4+1]*inv, a2=v[it*4+2]*inv, a3=v[it*4+3]*inv;
        rd += a0*bv4.x + a1*bv4.y + a2*bv4.z + a3*bv4.w;
        __align__(8) __half hv[4];
        hv[0]=__float2half_rn(a0); hv[1]=__float2half_rn(a1);
        hv[2]=__float2half_rn(a2); hv[3]=__float2half_rn(a3);
        *(uint2*)(ah + rb + lane*4 + it*128) = *(uint2*)hv;
    }
    rd = wred_sum(rd);
    if(lane==0) r[(size_t)b*CC + row] = rd;
}

// ============================================================================
// fp16 split GEMM: BM=BN=128, BK=32, 8 warps of 64x32, 2-stage cp.async.
// NPROD=1: ah*bh. NPROD=2: +ah*bl. NPROD=3: +al*bh.
// MODE 0: split fp16 hi/lo; 1: dots; 2: +r fp32; 3: fp32 partial (SYM);
// MODE 4: fp16 hi only.
// LAYB=0 NT (80B rows); LAYB=1 NN (272B rows, ldmatrix.trans).
// SMEM compact: A@0, [A-lo@TILE if NPROD==3], Bh@BHO, [Bl@BHO+BT if NPROD>=2]
// ============================================================================
#define BROW_NN 272

template<int MODE, int NPROD, int SYM, int LAYB>
__global__ __launch_bounds__(256,2) void k_wmma_nt(
    const __half* __restrict__ Ah, const __half* __restrict__ Al, size_t strA,
    const __half* __restrict__ Bh, const __half* __restrict__ Bl, size_t strB,
    int K, int ldka, int ldkb,
    void* out1, void* out2, size_t strO, int ldo,
    const float* __restrict__ vu, const float* __restrict__ vw,
    const float* __restrict__ vbq, const float* __restrict__ vbk,
    const float* __restrict__ vr)
{
    constexpr int ROWB = 80;
    constexpr int TILE = 128*ROWB;               // 10240
    constexpr int BT_NN = 32*BROW_NN;            // 8704
    constexpr int BHO = (NPROD==3) ? 2*TILE : TILE;
    constexpr int BT = (LAYB==0) ? TILE : BT_NN;
    constexpr int STG = BHO + ((NPROD>=2) ? 2 : 1)*BT;

    extern __shared__ __align__(128) unsigned char smem[];
    const uint32_t sb = smem_u32(smem);
    const int tid = threadIdx.x, lane = tid&31, wid = tid>>5;
    const int b = blockIdx.z;
    int m0, n0; size_t koff;
    if(SYM){
        const int t = blockIdx.x;
        const int ti = t<4?0 : (t<7?1 : (t<9?2:3));
        const int tj = t - (ti==0?0 : (ti==1?3 : (ti==2?5:6)));
        m0 = ti*128; n0 = tj*128;
        koff = (size_t)blockIdx.y * K;
    } else {
        m0 = blockIdx.y*128; n0 = blockIdx.x*128; koff = 0;
    }

    const int r = tid>>1, h = tid&1;
    const __half* gA0 = Ah + strA*b + (size_t)(m0+r)*ldka + koff + h*16;
    const __half* gA1 = (NPROD==3) ? (Al + strA*b + (size_t)(m0+r)*ldka + koff + h*16) : nullptr;
    const __half* gB0;
    const __half* gB1 = nullptr;
    uint32_t sdstB;
    if(LAYB==0){
        gB0 = Bh + strB*b + (size_t)(n0+r)*ldkb + koff + h*16;
        if(NPROD>=2) gB1 = Bl + strB*b + (size_t)(n0+r)*ldkb + koff + h*16;
        sdstB = sb + BHO + (uint32_t)(r*80 + h*32);
    } else {
        const int kr = tid>>3, cg = tid&7;
        gB0 = Bh + strB*b + (size_t)kr*ldkb + n0 + cg*16;
        if(NPROD>=2) gB1 = Bl + strB*b + (size_t)kr*ldkb + n0 + cg*16;
        sdstB = sb + BHO + (uint32_t)(kr*BROW_NN + cg*32);
    }
    const uint32_t sdstA = sb + (uint32_t)(r*80 + h*32);

    auto load_chunk = [&](int c){
        const uint32_t so = (uint32_t)(c&1)*STG;
        const size_t koA = (size_t)c*32;
        cpa16(sdstA+so,    gA0+koA); cpa16(sdstA+so+16, gA0+koA+8);
        if(NPROD==3){ cpa16(sdstA+so+TILE, gA1+koA); cpa16(sdstA+so+TILE+16, gA1+koA+8); }
        if(LAYB==0){
            cpa16(sdstB+so,    gB0+koA); cpa16(sdstB+so+16, gB0+koA+8);
            if(NPROD>=2){ cpa16(sdstB+so+BT, gB1+koA); cpa16(sdstB+so+BT+16, gB1+koA+8); }
        } else {
            const size_t koB = (size_t)c*32*ldkb;
            cpa16(sdstB+so,    gB0+koB); cpa16(sdstB+so+16, gB0+koB+8);
            if(NPROD>=2){ cpa16(sdstB+so+BT, gB1+koB); cpa16(sdstB+so+BT+16, gB1+koB+8); }
        }
        cpa_commit();
    };
    load_chunk(0);

    const int wm = wid&1, wn = wid>>1;
    const int lr16 = lane&15, lkc = lane>>4;
    float acc[4][4][4];
    #pragma unroll
    for(int i=0;i<4;i++)
        #pragma unroll
        for(int j=0;j<4;j++){ acc[i][j][0]=0.f; acc[i][j][1]=0.f; acc[i][j][2]=0.f; acc[i][j][3]=0.f; }

    const int nch = K/32;
    for(int c=0;c<nch;c++){
        if(c+1 < nch){ load_chunk(c+1); cpa_wait<1>(); }
        else         { cpa_wait<0>(); }
        __syncthreads();
        const uint32_t sbase = sb + (uint32_t)(c&1)*STG;
        #pragma unroll
        for(int ks=0; ks<2; ks++){
            const uint32_t coff = (uint32_t)((ks*2 + lkc)*16);
            uint32_t ahf[4][4], bhf[2][4], blf[2][4];
            #pragma unroll
            for(int mt=0; mt<4; mt++){
                const uint32_t a = sbase + (uint32_t)((wm*64 + mt*16 + lr16)*80) + coff;
                ldsm4(ahf[mt], a);
            }
            if(LAYB==0){
                #pragma unroll
                for(int g=0; g<2; g++){
                    const uint32_t a = sbase + BHO + (uint32_t)((wn*32 + g*16 + lr16)*80) + coff;
                    ldsm4(bhf[g], a);
                    if(NPROD>=2) ldsm4(blf[g], a + BT);
                }
            } else {
                #pragma unroll
                for(int g=0; g<2; g++){
                    const uint32_t a = sbase + BHO
                        + (uint32_t)((ks*16 + lr16)*BROW_NN)
                        + (uint32_t)((wn*32 + g*16 + lkc*8)*2);
                    ldsm4t(bhf[g], a);
                    if(NPROD>=2) ldsm4t(blf[g], a + BT);
                }
            }
            #pragma unroll
            for(int mt=0; mt<4; mt++)
                #pragma unroll
                for(int nt=0; nt<4; nt++){
                    const int g = nt>>1, p = nt&1;
                    const uint32_t h0 = LAYB ? bhf[g][p*2]   : bhf[g][p];
                    const uint32_t h1 = LAYB ? bhf[g][p*2+1] : bhf[g][p+2];
                    mma16816(acc[mt][nt], ahf[mt], h0, h1);
                    if(NPROD>=2){
                        const uint32_t l0 = LAYB ? blf[g][p*2]   : blf[g][p];
                        const uint32_t l1 = LAYB ? blf[g][p*2+1] : blf[g][p+2];
                        mma16816(acc[mt][nt], ahf[mt], l0, l1);
                    }
                }
            if(NPROD==3){
                uint32_t alf[4][4];
                #pragma unroll
                for(int mt=0; mt<4; mt++){
                    const uint32_t a = sbase + TILE + (uint32_t)((wm*64 + mt*16 + lr16)*80) + coff;
                    ldsm4(alf[mt], a);
                }
                #pragma unroll
                for(int mt=0; mt<4; mt++)
                    #pragma unroll
                    for(int nt=0; nt<4; nt++){
                        const int g = nt>>1, p = nt&1;
                        const uint32_t h0 = LAYB ? bhf[g][p*2]   : bhf[g][p];
                        const uint32_t h1 = LAYB ? bhf[g][p*2+1] : bhf[g][p+2];
                        mma16816(acc[mt][nt], alf[mt], h0, h1);
                    }
            }
        }
        __syncthreads();
    }

    const int er = lane>>2, ec = (lane&3)*2;
    if(MODE == 3){
        float* oF = (float*)out1
            + ((size_t)(blockIdx.y*10u + blockIdx.x)*gridDim.z + b)*16384u;
        #pragma unroll
        for(int mt=0; mt<4; mt++){
            const int m = wm*64 + mt*16 + er;
            #pragma unroll
            for(int nt=0; nt<4; nt++){
                const int n = wn*32 + nt*8 + ec;
                const float* d = acc[mt][nt];
                *(float2*)(oF + (size_t)m*128 + n)     = make_float2(d[0], d[1]);
                *(float2*)(oF + (size_t)(m+8)*128 + n) = make_float2(d[2], d[3]);
            }
        }
        return;
    }
    const int mW = m0 + wm*64, nW = n0 + wn*32;
    if(MODE == 0){
        __half* oH = (__half*)out1 + strO*b;
        __half* oL = (__half*)out2 + strO*b;
        #pragma unroll
        for(int mt=0; mt<4; mt++){
            const int m = mW + mt*16 + er;
            #pragma unroll
            for(int nt=0; nt<4; nt++){
                const int n = nW + nt*8 + ec;
                const float* d = acc[mt][nt];
                __half h0,l0,h1,l1;
                split2h(d[0],h0,l0); split2h(d[1],h1,l1);
                *(__half2*)(oH + (size_t)m*ldo + n) = __halves2half2(h0,h1);
                *(__half2*)(oL + (size_t)m*ldo + n) = __halves2half2(l0,l1);
                split2h(d[2],h0,l0); split2h(d[3],h1,l1);
                *(__half2*)(oH + (size_t)(m+8)*ldo + n) = __halves2half2(h0,h1);
                *(__half2*)(oL + (size_t)(m+8)*ldo + n) = __halves2half2(l0,l1);
            }
        }
    } else if(MODE == 4){
        __half* oH = (__half*)out1 + strO*b;
        #pragma unroll
        for(int mt=0; mt<4; mt++){
            const int m = mW + mt*16 + er;
            #pragma unroll
            for(int nt=0; nt<4; nt++){
                const int n = nW + nt*8 + ec;
                const float* d = acc[mt][nt];
                *(__half2*)(oH + (size_t)m*ldo + n) =
                    __halves2half2(__float2half_rn(d[0]), __float2half_rn(d[1]));
                *(__half2*)(oH + (size_t)(m+8)*ldo + n) =
                    __halves2half2(__float2half_rn(d[2]), __float2half_rn(d[3]));
            }
        }
    } else if(MODE == 1){
        float* oF = (float*)out1 + strO*b;
        #pragma unroll
        for(int mt=0; mt<4; mt++){
            const int m = mW + mt*16 + er;
            const float u0 = vu[(size_t)b*CC + m],   u1 = vu[(size_t)b*CC + m + 8];
            const float q0 = vbq[m],                 q1 = vbq[m + 8];
            #pragma unroll
            for(int nt=0; nt<4; nt++){
                const int n = nW + nt*8 + ec;
                const float2 bk2 = *(const float2*)(vbk + n);
                const float2 w2  = *(const float2*)(vw + (size_t)b*CC + n);
                const float t0 = w2.x + 4096.0f*bk2.x, t1 = w2.y + 4096.0f*bk2.y;
                const float* d = acc[mt][nt];
                float2 o0, o1;
                o0.x = (d[0] + u0*bk2.x + q0*t0)*0.125f;
                o0.y = (d[1] + u0*bk2.y + q0*t1)*0.125f;
                o1.x = (d[2] + u1*bk2.x + q1*t0)*0.125f;
                o1.y = (d[3] + u1*bk2.y + q1*t1)*0.125f;
                *(float2*)(oF + (size_t)m*ldo + n)     = o0;
                *(float2*)(oF + (size_t)(m+8)*ldo + n) = o1;
            }
        }
    } else {
        float* oF = (float*)out1 + strO*b;
        #pragma unroll
        for(int mt=0; mt<4; mt++){
            const int m = mW + mt*16 + er;
            const float r0 = vr[(size_t)b*CC + m], r1 = vr[(size_t)b*CC + m + 8];
            #pragma unroll
            for(int nt=0; nt<4; nt++){
                const int n = nW + nt*8 + ec;
                const float* d = acc[mt][nt];
                *(float2*)(oF + (size_t)m*ldo + n)     = make_float2(d[0]+r0, d[1]+r0);
                *(float2*)(oF + (size_t)(m+8)*ldo + n) = make_float2(d[2]+r1, d[3]+r1);
            }
        }
    }
}

// ============================================================================
// G reduce: sum 2 K-slice partials, split fp16 hi/lo, write tile + mirror.
// ============================================================================
__global__ __launch_bounds__(256) void k_gsum(
    const float* __restrict__ P, __half* __restrict__ Gh, __half* __restrict__ Gl)
{
    extern __shared__ float sm[];
    const int t = blockIdx.x, b = blockIdx.y;
    const int ti = t<4?0 : (t<7?1 : (t<9?2:3));
    const int tj = t - (ti==0?0 : (ti==1?3 : (ti==2?5:6)));
    const int tid = threadIdx.x;
    const float4* p4 = (const float4*)P;
    #pragma unroll
    for(int v=0; v<16; v++){
        const int f4 = v*256 + tid;
        float4 a = make_float4(0.f,0.f,0.f,0.f);
        #pragma unroll
        for(int s=0;s<2;s++){
            float4 q = p4[(size_t)((s*10 + t)*BB + b)*4096u + f4];
            a.x+=q.x; a.y+=q.y; a.z+=q.z; a.w+=q.w;
        }
        const int e = f4*4, m = e>>7, n = e&127;
        sm[m*129+n]=a.x; sm[m*129+n+1]=a.y; sm[m*129+n+2]=a.z; sm[m*129+n+3]=a.w;
    }
    __syncthreads();
    const int M0 = ti*128, N0 = tj*128;
    __half* GhB = Gh + (size_t)b*CC*CC;
    __half* GlB = Gl + (size_t)b*CC*CC;
    #pragma unroll
    for(int v=0; v<32; v++){
        const int h2 = v*256 + tid;
        const int m = h2>>6, n2 = h2&63;
        __half h0,l0,h1,l1;
        split2h(sm[m*129 + 2*n2],     h0,l0);
        split2h(sm[m*129 + 2*n2 + 1], h1,l1);
        const size_t o = (size_t)(M0+m)*CC + N0 + 2*n2;
        *(__half2*)(GhB+o) = __halves2half2(h0,h1);
        *(__half2*)(GlB+o) = __halves2half2(l0,l1);
    }
    if(ti != tj){
        #pragma unroll
        for(int v=0; v<32; v++){
            const int h2 = v*256 + tid;
            const int mr = h2>>6, c2 = h2&63;
            __half h0,l0,h1,l1;
            split2h(sm[(2*c2)*129 + mr],   h0,l0);
            split2h(sm[(2*c2+1)*129 + mr], h1,l1);
            const size_t o = (size_t)(N0+mr)*CC + M0 + 2*c2;
            *(__half2*)(GhB+o) = __halves2half2(h0,h1);
            *(__half2*)(GlB+o) = __halves2half2(l0,l1);
        }
    }
}

// ============================================================================
extern "C" void kernel_launch(void* const* d_in, const int* in_sizes, int n_in,
                              void* d_out, int out_size)
{
    const float* x  = (const float*)d_in[0];
    const float* Wq = (const float*)d_in[1];
    const float* bq = (const float*)d_in[2];
    const float* Wk = (const float*)d_in[3];
    const float* bk = (const float*)d_in[4];
    const float* Wv = (const float*)d_in[5];
    const float* bv = (const float*)d_in[6];
    float* out = (float*)d_out;

    void* basep = nullptr;
    cudaGetSymbolAddress(&basep, g_scr);
    unsigned char* base = (unsigned char*)basep;

    const size_t XE = (size_t)BB*CC*TT;
    const size_t WE = (size_t)CC*CC;
    const size_t GE = (size_t)BB*CC*CC;
    size_t off = 0;
    auto take = [&](size_t bytes){ size_t o = off; off += (bytes + 255) & ~(size_t)255; return o; };
    __half* xh  = (__half*)(base + take(XE*2));
    __half* wqh = (__half*)(base + take(WE*2));
    __half* wql = (__half*)(base + take(WE*2));
    __half* wkh = (__half*)(base + take(WE*2));
    __half* wkl = (__half*)(base + take(WE*2));
    __half* wvth= (__half*)(base + take(WE*2));
    __half* Gh  = (__half*)(base + take(GE*2));
    __half* Gl  = (__half*)(base + take(GE*2));
    __half* Hh  = (__half*)(base + take(GE*2));
    __half* Hl  = (__half*)(base + take(GE*2));
    __half* Mh  = (__half*)(base + take(GE*2));
    __half* ah  = (__half*)(base + take(GE*2));
    float* dots = (float*)(base + take(GE*4));
    float* Gpart= (float*)(base + take((size_t)2*10*BB*16384*4));
    float* s    = (float*)(base + take((size_t)BB*CC*4));
    float* u    = (float*)(base + take((size_t)BB*CC*4));
    float* w    = (float*)(base + take((size_t)BB*CC*4));
    float* rr   = (float*)(base + take((size_t)BB*CC*4));

    // smem: H/dots (NPROD=3): 81920; G/M (NPROD=1 NT): 40960; out (NPROD=1 NN): 37888
    cudaFuncSetAttribute(k_wmma_nt<0,3,0,0>, cudaFuncAttributeMaxDynamicSharedMemorySize, 81920);
    cudaFuncSetAttribute(k_wmma_nt<1,3,0,0>, cudaFuncAttributeMaxDynamicSharedMemorySize, 81920);
    cudaFuncSetAttribute(k_wmma_nt<4,1,0,0>, cudaFuncAttributeMaxDynamicSharedMemorySize, 40960);
    cudaFuncSetAttribute(k_wmma_nt<2,1,0,1>, cudaFuncAttributeMaxDynamicSharedMemorySize, 37888);
    cudaFuncSetAttribute(k_wmma_nt<3,1,1,0>, cudaFuncAttributeMaxDynamicSharedMemorySize, 40960);
    cudaFuncSetAttribute(k_gsum, cudaFuncAttributeMaxDynamicSharedMemorySize, 66048);

    dim3 blk(256,1,1);
    k_split_x<<<dim3(CC, BB), blk>>>(x, xh, s);
    k_split_w<<<dim3(CC*CC/1024, 2, 1), blk>>>(Wq, Wk, wqh, wql, wkh, wkl);
    k_split_wT<<<dim3(CC/128, CC/32, 1), blk>>>(Wv, wvth);
    k_uw<<<dim3(CC/8, 2, BB), blk>>>(Wq, Wk, s, u, w);
    // G partials: upper tiles, NPROD=1 (xh*xh^T), split-K x2, BK=32
    k_wmma_nt<3,1,1,0><<<dim3(10, 2, BB), blk, 40960>>>(
        xh, nullptr, (size_t)CC*TT, xh, nullptr, (size_t)CC*TT, 2048, TT, TT,
        Gpart, nullptr, 0, 128, nullptr,nullptr,nullptr,nullptr,nullptr);
    k_gsum<<<dim3(10, BB), blk, 66048>>>(Gpart, Gh, Gl);
    // H = Wq G (G symmetric -> NT; 3 products) -> Hh,Hl
    k_wmma_nt<0,3,0,0><<<dim3(CC/128, CC/128, BB), blk, 81920>>>(
        wqh, wql, (size_t)0, Gh, Gl, (size_t)CC*CC, CC, CC, CC,
        Hh, Hl, (size_t)CC*CC, CC, nullptr,nullptr,nullptr,nullptr,nullptr);
    // dots = H Wk^T + rank-1, scaled (3 products)
    k_wmma_nt<1,3,0,0><<<dim3(CC/128, CC/128, BB), blk, 81920>>>(
        Hh, Hl, (size_t)CC*CC, wkh, wkl, (size_t)0, CC, CC, CC,
        dots, nullptr, (size_t)CC*CC, CC, u, w, bq, bk, nullptr);
    // softmax -> ah ; r = attn.bv
    k_softmax<<<dim3(CC/8, BB), blk>>>(dots, ah, bv, rr);
    // M = ah WvT^T (1 product), fp16-hi out
    k_wmma_nt<4,1,0,0><<<dim3(CC/128, CC/128, BB), blk, 40960>>>(
        ah, nullptr, (size_t)CC*CC, wvth, nullptr, (size_t)0, CC, CC, CC,
        Mh, nullptr, (size_t)CC*CC, CC, nullptr,nullptr,nullptr,nullptr,nullptr);
    // out = Mh xh + r  (NN, single product, BK=32)
    k_wmma_nt<2,1,0,1><<<dim3(TT/128, CC/128, BB), blk, 37888>>>(
        Mh, nullptr, (size_t)CC*CC, xh, nullptr, (size_t)CC*TT, 512, CC, TT,
        out, nullptr, (size_t)CC*TT, TT, nullptr,nullptr,nullptr,nullptr, rr);
}

// round 17
// speedup vs baseline: 1.0846x; 1.0129x over previous
#include <cuda_runtime.h>
#include <cuda_fp16.h>
#include <math.h>
#include <stdint.h>

#define BB 8
#define CC 512
#define TT 4096

static __device__ __align__(256) unsigned char g_scr[232u*1024u*1024u];

// ============================ helpers =======================================
__device__ __forceinline__ uint32_t smem_u32(const void* p){
    uint32_t a;
    asm("{ .reg .u64 t; cvta.to.shared.u64 t, %1; cvt.u32.u64 %0, t; }" : "=r"(a) : "l"(p));
    return a;
}
__device__ __forceinline__ void cpa16(uint32_t s, const void* g){
    asm volatile("cp.async.cg.shared.global [%0], [%1], 16;" :: "r"(s), "l"(g));
}
__device__ __forceinline__ void cpa_commit(){ asm volatile("cp.async.commit_group;" ::: "memory"); }
template<int N> __device__ __forceinline__ void cpa_wait(){
    asm volatile("cp.async.wait_group %0;" :: "n"(N) : "memory");
}
__device__ __forceinline__ void ldsm4(uint32_t* r, uint32_t addr){
    asm volatile("ldmatrix.sync.aligned.m8n8.x4.shared.b16 {%0,%1,%2,%3}, [%4];"
        : "=r"(r[0]), "=r"(r[1]), "=r"(r[2]), "=r"(r[3]) : "r"(addr));
}
__device__ __forceinline__ void ldsm4t(uint32_t* r, uint32_t addr){
    asm volatile("ldmatrix.sync.aligned.m8n8.x4.trans.shared.b16 {%0,%1,%2,%3}, [%4];"
        : "=r"(r[0]), "=r"(r[1]), "=r"(r[2]), "=r"(r[3]) : "r"(addr));
}
__device__ __forceinline__ void mma16816(float* d, const uint32_t* a, uint32_t b0, uint32_t b1){
    asm volatile("mma.sync.aligned.m16n8k16.row.col.f32.f16.f16.f32 "
        "{%0,%1,%2,%3}, {%4,%5,%6,%7}, {%8,%9}, {%0,%1,%2,%3};"
        : "+f"(d[0]), "+f"(d[1]), "+f"(d[2]), "+f"(d[3])
        : "r"(a[0]), "r"(a[1]), "r"(a[2]), "r"(a[3]), "r"(b0), "r"(b1));
}
__device__ __forceinline__ void split2h(float f, __half &h, __half &l){
    h = __float2half_rn(f);
    l = __float2half_rn(f - __half2float(h));
}
__device__ __forceinline__ float wred_sum(float v){
    #pragma unroll
    for(int o=16;o;o>>=1) v += __shfl_xor_sync(0xffffffffu, v, o);
    return v;
}
__device__ __forceinline__ float wred_max(float v){
    #pragma unroll
    for(int o=16;o;o>>=1) v = fmaxf(v, __shfl_xor_sync(0xffffffffu, v, o));
    return v;
}

// ============================================================================
// Split x elementwise: xh [b,c,t] (hi only); s[b,c] = rowsum
// ============================================================================
__global__ __launch_bounds__(256) void k_split_x(
    const float* __restrict__ x,
    __half* __restrict__ xh,
    float* __restrict__ s)
{
    __shared__ float wsum[8];
    const int c = blockIdx.x, b = blockIdx.y;
    const int tid = threadIdx.x;
    const size_t rb = ((size_t)b*CC + c)*TT;
    float sum = 0.f;
    #pragma unroll
    for(int it=0; it<4; it++){
        const int idx = (it*256 + tid)*4;
        float4 v = *(const float4*)(x + rb + idx);
        __align__(8) __half hv[4];
        hv[0]=__float2half_rn(v.x); hv[1]=__float2half_rn(v.y);
        hv[2]=__float2half_rn(v.z); hv[3]=__float2half_rn(v.w);
        *(uint2*)(xh + rb + idx) = *(uint2*)hv;
        sum += v.x + v.y + v.z + v.w;
    }
    sum = wred_sum(sum);
    if((tid&31)==0) wsum[tid>>5] = sum;
    __syncthreads();
    if(tid==0){
        float t = 0.f;
        #pragma unroll
        for(int i=0;i<8;i++) t += wsum[i];
        s[(size_t)b*CC + c] = t;
    }
}

// ============================================================================
// Merged prep: blocks [0,512) split Wq/Wk hi+lo; [512,576) transpose Wv hi;
// [576,1600) u = Wq s, w = Wk s
// ============================================================================
__global__ __launch_bounds__(256) void k_prep(
    const float* __restrict__ Wq, const float* __restrict__ Wk,
    const float* __restrict__ Wv, const float* __restrict__ s,
    __half* __restrict__ qh, __half* __restrict__ ql,
    __half* __restrict__ kh, __half* __restrict__ kl,
    __half* __restrict__ wvth,
    float* __restrict__ u, float* __restrict__ w)
{
    __shared__ float tile[32][129];
    const int blk = blockIdx.x;
    const int tid = threadIdx.x;
    if(blk < 512){
        const int which = blk >> 8;
        const float* W = which ? Wk : Wq;
        __half* oh = which ? kh : qh;
        __half* ol = which ? kl : ql;
        size_t i = ((size_t)(blk & 255)*256 + tid)*4;
        float4 v = *(const float4*)(W + i);
        __align__(8) __half hv[4], lv[4];
        split2h(v.x,hv[0],lv[0]); split2h(v.y,hv[1],lv[1]);
        split2h(v.z,hv[2],lv[2]); split2h(v.w,hv[3],lv[3]);
        *(uint2*)(oh+i) = *(uint2*)hv;
        *(uint2*)(ol+i) = *(uint2*)lv;
    } else if(blk < 576){
        const int t = blk - 512;
        const int o0 = (t & 3)*128, d0 = (t >> 2)*32;
        const int tx = tid & 31, ty = tid >> 5;
        #pragma unroll
        for(int i=0;i<4;i++){
            const int dl = ty + 8*i;
            float4 v = *(const float4*)(Wv + (size_t)(d0+dl)*CC + o0 + tx*4);
            tile[dl][tx*4+0]=v.x; tile[dl][tx*4+1]=v.y;
            tile[dl][tx*4+2]=v.z; tile[dl][tx*4+3]=v.w;
        }
        __syncthreads();
        const int r = tid>>1, h = tid&1;
        __align__(16) __half hv[16];
        #pragma unroll
        for(int j=0;j<16;j++) hv[j] = __float2half_rn(tile[h*16+j][r]);
        size_t ob = (size_t)(o0 + r)*CC + d0 + h*16;
        *(uint4*)(wvth+ob)   = *(uint4*)hv;
        *(uint4*)(wvth+ob+8) = *(uint4*)(hv+8);
    } else {
        const int t = blk - 576;
        const int which = (t>>6) & 1;
        const int b = t >> 7;
        const float* __restrict__ W = which ? Wk : Wq;
        const int o = (t & 63)*8 + (tid>>5);
        const int lane = tid & 31;
        const float* __restrict__ sp = s + (size_t)b*CC;
        float acc = 0.f;
        #pragma unroll
        for(int it=0; it<4; it++){
            int c = lane*4 + it*128;
            float4 wv = *(const float4*)(W + (size_t)o*CC + c);
            float4 sv = *(const float4*)(sp + c);
            acc += wv.x*sv.x + wv.y*sv.y + wv.z*sv.z + wv.w*sv.w;
        }
        acc = wred_sum(acc);
        if(lane==0) (which ? w : u)[(size_t)b*CC + o] = acc;
    }
}

// row softmax over 512; attn -> ah (fp16 hi only); r = attn . bv
__global__ __launch_bounds__(256) void k_softmax(
    const float* __restrict__ dots,
    __half* __restrict__ ah,
    const float* __restrict__ bv, float* __restrict__ r)
{
    const int b = blockIdx.y;
    const int row = blockIdx.x*8 + (threadIdx.x>>5);
    const int lane = threadIdx.x & 31;
    const float* __restrict__ dr = dots + ((size_t)b*CC + row)*CC;
    float v[16];
    float mx = -1e30f;
    #pragma unroll
    for(int it=0; it<4; it++){
        float4 t = *(const float4*)(dr + lane*4 + it*128);
        v[it*4+0]=t.x; v[it*4+1]=t.y; v[it*4+2]=t.z; v[it*4+3]=t.w;
        mx = fmaxf(mx, fmaxf(fmaxf(t.x,t.y), fmaxf(t.z,t.w)));
    }
    mx = wred_max(mx);
    float sum = 0.f;
    #pragma unroll
    for(int j=0;j<16;j++){ v[j] = expf(v[j]-mx); sum += v[j]; }
    sum = wred_sum(sum);
    const float inv = 1.f/sum;
    float rd = 0.f;
    size_t rb = ((size_t)b*CC + row)*CC;
    #pragma unroll
    for(int it=0; it<4; it++){
        float4 bv4 = *(const float4*)(bv + lane*4 + it*128);
        float a0=v[it*4+0]*inv, a1=v[it*4+1]*inv, a2=v[it*4+2]*inv, a3=v[it*4+3]*inv;
        rd += a0*bv4.x + a1*bv4.y + a2*bv4.z + a3*bv4.w;
        __align__(8) __half hv[4];
        hv[0]=__float2half_rn(a0); hv[1]=__float2half_rn(a1);
        hv[2]=__float2half_rn(a2); hv[3]=__float2half_rn(a3);
        *(uint2*)(ah + rb + lane*4 + it*128) = *(uint2*)hv;
    }
    rd = wred_sum(rd);
    if(lane==0) r[(size_t)b*CC + row] = rd;
}

// ============================================================================
// fp16 split GEMM: BM=BN=128, BK=32, 8 warps of 64x32, 2-stage cp.async.
// NPROD=1: ah*bh. NPROD=2: +ah*bl. NPROD=3: +ah*bl+al*bh.
// MODE 0: split fp16 hi/lo; 1: dots; 2: +r fp32; 3: fp32 partial (SYM);
// MODE 4: fp16 hi only.
// LAYB=0 NT (80B rows); LAYB=1 NN (272B rows, ldmatrix.trans).
// SMEM compact: A@0, [A-lo@TILE if NPROD==3], Bh@BHO, [Bl@BHO+BT if NPROD>=2]
// ============================================================================
#define BROW_NN 272

template<int MODE, int NPROD, int SYM, int LAYB>
__global__ __launch_bounds__(256,2) void k_wmma_nt(
    const __half* __restrict__ Ah, const __half* __restrict__ Al, size_t strA,
    const __half* __restrict__ Bh, const __half* __restrict__ Bl, size_t strB,
    int K, int ldka, int ldkb,
    void* out1, void* out2, size_t strO, int ldo,
    const float* __restrict__ vu, const float* __restrict__ vw,
    const float* __restrict__ vbq, const float* __restrict__ vbk,
    const float* __restrict__ vr)
{
    constexpr int ROWB = 80;
    constexpr int TILE = 128*ROWB;               // 10240
    constexpr int BT_NN = 32*BROW_NN;            // 8704
    constexpr int BHO = (NPROD==3) ? 2*TILE : TILE;
    constexpr int BT = (LAYB==0) ? TILE : BT_NN;
    constexpr int STG = BHO + ((NPROD>=2) ? 2 : 1)*BT;

    extern __shared__ __align__(128) unsigned char smem[];
    const uint32_t sb = smem_u32(smem);
    const int tid = threadIdx.x, lane = tid&31, wid = tid>>5;
    const int b = blockIdx.z;
    int m0, n0; size_t koff;
    if(SYM){
        const int t = blockIdx.x;
        const int ti = t<4?0 : (t<7?1 : (t<9?2:3));
        const int tj = t - (ti==0?0 : (ti==1?3 : (ti==2?5:6)));
        m0 = ti*128; n0 = tj*128;
        koff = (size_t)blockIdx.y * K;
    } else {
        m0 = blockIdx.y*128; n0 = blockIdx.x*128; koff = 0;
    }

    const int r = tid>>1, h = tid&1;
    const __half* gA0 = Ah + strA*b + (size_t)(m0+r)*ldka + koff + h*16;
    const __half* gA1 = (NPROD==3) ? (Al + strA*b + (size_t)(m0+r)*ldka + koff + h*16) : nullptr;
    const __half* gB0;
    const __half* gB1 = nullptr;
    uint32_t sdstB;
    if(LAYB==0){
        gB0 = Bh + strB*b + (size_t)(n0+r)*ldkb + koff + h*16;
        if(NPROD>=2) gB1 = Bl + strB*b + (size_t)(n0+r)*ldkb + koff + h*16;
        sdstB = sb + BHO + (uint32_t)(r*80 + h*32);
    } else {
        const int kr = tid>>3, cg = tid&7;
        gB0 = Bh + strB*b + (size_t)kr*ldkb + n0 + cg*16;
        if(NPROD>=2) gB1 = Bl + strB*b + (size_t)kr*ldkb + n0 + cg*16;
        sdstB = sb + BHO + (uint32_t)(kr*BROW_NN + cg*32);
    }
    const uint32_t sdstA = sb + (uint32_t)(r*80 + h*32);

    auto load_chunk = [&](int c){
        const uint32_t so = (uint32_t)(c&1)*STG;
        const size_t koA = (size_t)c*32;
        cpa16(sdstA+so,    gA0+koA); cpa16(sdstA+so+16, gA0+koA+8);
        if(NPROD==3){ cpa16(sdstA+so+TILE, gA1+koA); cpa16(sdstA+so+TILE+16, gA1+koA+8); }
        if(LAYB==0){
            cpa16(sdstB+so,    gB0+koA); cpa16(sdstB+so+16, gB0+koA+8);
            if(NPROD>=2){ cpa16(sdstB+so+BT, gB1+koA); cpa16(sdstB+so+BT+16, gB1+koA+8); }
        } else {
            const size_t koB = (size_t)c*32*ldkb;
            cpa16(sdstB+so,    gB0+koB); cpa16(sdstB+so+16, gB0+koB+8);
            if(NPROD>=2){ cpa16(sdstB+so+BT, gB1+koB); cpa16(sdstB+so+BT+16, gB1+koB+8); }
        }
        cpa_commit();
    };
    load_chunk(0);

    const int wm = wid&1, wn = wid>>1;
    const int lr16 = lane&15, lkc = lane>>4;
    float acc[4][4][4];
    #pragma unroll
    for(int i=0;i<4;i++)
        #pragma unroll
        for(int j=0;j<4;j++){ acc[i][j][0]=0.f; acc[i][j][1]=0.f; acc[i][j][2]=0.f; acc[i][j][3]=0.f; }

    const int nch = K/32;
    for(int c=0;c<nch;c++){
        if(c+1 < nch){ load_chunk(c+1); cpa_wait<1>(); }
        else         { cpa_wait<0>(); }
        __syncthreads();
        const uint32_t sbase = sb + (uint32_t)(c&1)*STG;
        #pragma unroll
        for(int ks=0; ks<2; ks++){
            const uint32_t coff = (uint32_t)((ks*2 + lkc)*16);
            uint32_t ahf[4][4], bhf[2][4], blf[2][4];
            #pragma unroll
            for(int mt=0; mt<4; mt++){
                const uint32_t a = sbase + (uint32_t)((wm*64 + mt*16 + lr16)*80) + coff;
                ldsm4(ahf[mt], a);
            }
            if(LAYB==0){
                #pragma unroll
                for(int g=0; g<2; g++){
                    const uint32_t a = sbase + BHO + (uint32_t)((wn*32 + g*16 + lr16)*80) + coff;
                    ldsm4(bhf[g], a);
                    if(NPROD>=2) ldsm4(blf[g], a + BT);
                }
            } else {
                #pragma unroll
                for(int g=0; g<2; g++){
                    const uint32_t a = sbase + BHO
                        + (uint32_t)((ks*16 + lr16)*BROW_NN)
                        + (uint32_t)((wn*32 + g*16 + lkc*8)*2);
                    ldsm4t(bhf[g], a);
                    if(NPROD>=2) ldsm4t(blf[g], a + BT);
                }
            }
            #pragma unroll
            for(int mt=0; mt<4; mt++)
                #pragma unroll
                for(int nt=0; nt<4; nt++){
                    const int g = nt>>1, p = nt&1;
                    const uint32_t h0 = LAYB ? bhf[g][p*2]   : bhf[g][p];
                    const uint32_t h1 = LAYB ? bhf[g][p*2+1] : bhf[g][p+2];
                    mma16816(acc[mt][nt], ahf[mt], h0, h1);
                    if(NPROD>=2){
                        const uint32_t l0 = LAYB ? blf[g][p*2]   : blf[g][p];
                        const uint32_t l1 = LAYB ? blf[g][p*2+1] : blf[g][p+2];
                        mma16816(acc[mt][nt], ahf[mt], l0, l1);
                    }
                }
            if(NPROD==3){
                uint32_t alf[4][4];
                #pragma unroll
                for(int mt=0; mt<4; mt++){
                    const uint32_t a = sbase + TILE + (uint32_t)((wm*64 + mt*16 + lr16)*80) + coff;
                    ldsm4(alf[mt], a);
                }
                #pragma unroll
                for(int mt=0; mt<4; mt++)
                    #pragma unroll
                    for(int nt=0; nt<4; nt++){
                        const int g = nt>>1, p = nt&1;
                        const uint32_t h0 = LAYB ? bhf[g][p*2]   : bhf[g][p];
                        const uint32_t h1 = LAYB ? bhf[g][p*2+1] : bhf[g][p+2];
                        mma16816(acc[mt][nt], alf[mt], h0, h1);
                    }
            }
        }
        __syncthreads();
    }

    const int er = lane>>2, ec = (lane&3)*2;
    if(MODE == 3){
        float* oF = (float*)out1
            + ((size_t)(blockIdx.y*10u + blockIdx.x)*gridDim.z + b)*16384u;
        #pragma unroll
        for(int mt=0; mt<4; mt++){
            const int m = wm*64 + mt*16 + er;
            #pragma unroll
            for(int nt=0; nt<4; nt++){
                const int n = wn*32 + nt*8 + ec;
                const float* d = acc[mt][nt];
                *(float2*)(oF + (size_t)m*128 + n)     = make_float2(d[0], d[1]);
                *(float2*)(oF + (size_t)(m+8)*128 + n) = make_float2(d[2], d[3]);
            }
        }
        return;
    }
    const int mW = m0 + wm*64, nW = n0 + wn*32;
    if(MODE == 0){
        __half* oH = (__half*)out1 + strO*b;
        __half* oL = (__half*)out2 + strO*b;
        #pragma unroll
        for(int mt=0; mt<4; mt++){
            const int m = mW + mt*16 + er;
            #pragma unroll
            for(int nt=0; nt<4; nt++){
                const int n = nW + nt*8 + ec;
                const float* d = acc[mt][nt];
                __half h0,l0,h1,l1;
                split2h(d[0],h0,l0); split2h(d[1],h1,l1);
                *(__half2*)(oH + (size_t)m*ldo + n) = __halves2half2(h0,h1);
                *(__half2*)(oL + (size_t)m*ldo + n) = __halves2half2(l0,l1);
                split2h(d[2],h0,l0); split2h(d[3],h1,l1);
                *(__half2*)(oH + (size_t)(m+8)*ldo + n) = __halves2half2(h0,h1);
                *(__half2*)(oL + (size_t)(m+8)*ldo + n) = __halves2half2(l0,l1);
            }
        }
    } else if(MODE == 4){
        __half* oH = (__half*)out1 + strO*b;
        #pragma unroll
        for(int mt=0; mt<4; mt++){
            const int m = mW + mt*16 + er;
            #pragma unroll
            for(int nt=0; nt<4; nt++){
                const int n = nW + nt*8 + ec;
                const float* d = acc[mt][nt];
                *(__half2*)(oH + (size_t)m*ldo + n) =
                    __halves2half2(__float2half_rn(d[0]), __float2half_rn(d[1]));
                *(__half2*)(oH + (size_t)(m+8)*ldo + n) =
                    __halves2half2(__float2half_rn(d[2]), __float2half_rn(d[3]));
            }
        }
    } else if(MODE == 1){
        float* oF = (float*)out1 + strO*b;
        #pragma unroll
        for(int mt=0; mt<4; mt++){
            const int m = mW + mt*16 + er;
            const float u0 = vu[(size_t)b*CC + m],   u1 = vu[(size_t)b*CC + m + 8];
            const float q0 = vbq[m],                 q1 = vbq[m + 8];
            #pragma unroll
            for(int nt=0; nt<4; nt++){
                const int n = nW + nt*8 + ec;
                const float2 bk2 = *(const float2*)(vbk + n);
                const float2 w2  = *(const float2*)(vw + (size_t)b*CC + n);
                const float t0 = w2.x + 4096.0f*bk2.x, t1 = w2.y + 4096.0f*bk2.y;
                const float* d = acc[mt][nt];
                float2 o0, o1;
                o0.x = (d[0] + u0*bk2.x + q0*t0)*0.125f;
                o0.y = (d[1] + u0*bk2.y + q0*t1)*0.125f;
                o1.x = (d[2] + u1*bk2.x + q1*t0)*0.125f;
                o1.y = (d[3] + u1*bk2.y + q1*t1)*0.125f;
                *(float2*)(oF + (size_t)m*ldo + n)     = o0;
                *(float2*)(oF + (size_t)(m+8)*ldo + n) = o1;
            }
        }
    } else {
        float* oF = (float*)out1 + strO*b;
        #pragma unroll
        for(int mt=0; mt<4; mt++){
            const int m = mW + mt*16 + er;
            const float r0 = vr[(size_t)b*CC + m], r1 = vr[(size_t)b*CC + m + 8];
            #pragma unroll
            for(int nt=0; nt<4; nt++){
                const int n = nW + nt*8 + ec;
                const float* d = acc[mt][nt];
                *(float2*)(oF + (size_t)m*ldo + n)     = make_float2(d[0]+r0, d[1]+r0);
                *(float2*)(oF + (size_t)(m+8)*ldo + n) = make_float2(d[2]+r1, d[3]+r1);
            }
        }
    }
}

// ============================================================================
// G reduce: sum 2 K-slice partials, split fp16 hi/lo, write tile + mirror.
// ============================================================================
__global__ __launch_bounds__(256) void k_gsum(
    const float* __restrict__ P, __half* __restrict__ Gh, __half* __restrict__ Gl)
{
    extern __shared__ float sm[];
    const int t = blockIdx.x, b = blockIdx.y;
    const int ti = t<4?0 : (t<7?1 : (t<9?2:3));
    const int tj = t - (ti==0?0 : (ti==1?3 : (ti==2?5:6)));
    const int tid = threadIdx.x;
    const float4* p4 = (const float4*)P;
    #pragma unroll
    for(int v=0; v<16; v++){
        const int f4 = v*256 + tid;
        float4 a = make_float4(0.f,0.f,0.f,0.f);
        #pragma unroll
        for(int s=0;s<2;s++){
            float4 q = p4[(size_t)((s*10 + t)*BB + b)*4096u + f4];
            a.x+=q.x; a.y+=q.y; a.z+=q.z; a.w+=q.w;
        }
        const int e = f4*4, m = e>>7, n = e&127;
        sm[m*129+n]=a.x; sm[m*129+n+1]=a.y; sm[m*129+n+2]=a.z; sm[m*129+n+3]=a.w;
    }
    __syncthreads();
    const int M0 = ti*128, N0 = tj*128;
    __half* GhB = Gh + (size_t)b*CC*CC;
    __half* GlB = Gl + (size_t)b*CC*CC;
    #pragma unroll
    for(int v=0; v<32; v++){
        const int h2 = v*256 + tid;
        const int m = h2>>6, n2 = h2&63;
        __half h0,l0,h1,l1;
        split2h(sm[m*129 + 2*n2],     h0,l0);
        split2h(sm[m*129 + 2*n2 + 1], h1,l1);
        const size_t o = (size_t)(M0+m)*CC + N0 + 2*n2;
        *(__half2*)(GhB+o) = __halves2half2(h0,h1);
        *(__half2*)(GlB+o) = __halves2half2(l0,l1);
    }
    if(ti != tj){
        #pragma unroll
        for(int v=0; v<32; v++){
            const int h2 = v*256 + tid;
            const int mr = h2>>6, c2 = h2&63;
            __half h0,l0,h1,l1;
            split2h(sm[(2*c2)*129 + mr],   h0,l0);
            split2h(sm[(2*c2+1)*129 + mr], h1,l1);
            const size_t o = (size_t)(N0+mr)*CC + M0 + 2*c2;
            *(__half2*)(GhB+o) = __halves2half2(h0,h1);
            *(__half2*)(GlB+o) = __halves2half2(l0,l1);
        }
    }
}

// ============================================================================
extern "C" void kernel_launch(void* const* d_in, const int* in_sizes, int n_in,
                              void* d_out, int out_size)
{
    const float* x  = (const float*)d_in[0];
    const float* Wq = (const float*)d_in[1];
    const float* bq = (const float*)d_in[2];
    const float* Wk = (const float*)d_in[3];
    const float* bk = (const float*)d_in[4];
    const float* Wv = (const float*)d_in[5];
    const float* bv = (const float*)d_in[6];
    float* out = (float*)d_out;

    void* basep = nullptr;
    cudaGetSymbolAddress(&basep, g_scr);
    unsigned char* base = (unsigned char*)basep;

    const size_t XE = (size_t)BB*CC*TT;
    const size_t WE = (size_t)CC*CC;
    const size_t GE = (size_t)BB*CC*CC;
    size_t off = 0;
    auto take = [&](size_t bytes){ size_t o = off; off += (bytes + 255) & ~(size_t)255; return o; };
    __half* xh  = (__half*)(base + take(XE*2));
    __half* wqh = (__half*)(base + take(WE*2));
    __half* wql = (__half*)(base + take(WE*2));
    __half* wkh = (__half*)(base + take(WE*2));
    __half* wkl = (__half*)(base + take(WE*2));
    __half* wvth= (__half*)(base + take(WE*2));
    __half* Gh  = (__half*)(base + take(GE*2));
    __half* Gl  = (__half*)(base + take(GE*2));
    __half* Hh  = (__half*)(base + take(GE*2));
    __half* Hl  = (__half*)(base + take(GE*2));
    __half* Mh  = (__half*)(base + take(GE*2));
    __half* ah  = (__half*)(base + take(GE*2));
    float* dots = (float*)(base + take(GE*4));
    float* Gpart= (float*)(base + take((size_t)2*10*BB*16384*4));
    float* s    = (float*)(base + take((size_t)BB*CC*4));
    float* u    = (float*)(base + take((size_t)BB*CC*4));
    float* w    = (float*)(base + take((size_t)BB*CC*4));
    float* rr   = (float*)(base + take((size_t)BB*CC*4));

    // smem: H/dots (NPROD=3): 81920; G/M (NPROD=1 NT): 40960; out (NPROD=1 NN): 37888
    cudaFuncSetAttribute(k_wmma_nt<0,3,0,0>, cudaFuncAttributeMaxDynamicSharedMemorySize, 81920);
    cudaFuncSetAttribute(k_wmma_nt<1,3,0,0>, cudaFuncAttributeMaxDynamicSharedMemorySize, 81920);
    cudaFuncSetAttribute(k_wmma_nt<4,1,0,0>, cudaFuncAttributeMaxDynamicSharedMemorySize, 40960);
    cudaFuncSetAttribute(k_wmma_nt<2,1,0,1>, cudaFuncAttributeMaxDynamicSharedMemorySize, 37888);
    cudaFuncSetAttribute(k_wmma_nt<3,1,1,0>, cudaFuncAttributeMaxDynamicSharedMemorySize, 40960);
    cudaFuncSetAttribute(k_gsum, cudaFuncAttributeMaxDynamicSharedMemorySize, 66048);

    dim3 blk(256,1,1);
    k_split_x<<<dim3(CC, BB), blk>>>(x, xh, s);
    // merged prep: W splits + Wv transpose + u/w
    k_prep<<<dim3(1600,1,1), blk>>>(Wq, Wk, Wv, s, wqh, wql, wkh, wkl, wvth, u, w);
    // G partials: upper tiles, NPROD=1 (xh*xh^T), split-K x2
    k_wmma_nt<3,1,1,0><<<dim3(10, 2, BB), blk, 40960>>>(
        xh, nullptr, (size_t)CC*TT, xh, nullptr, (size_t)CC*TT, 2048, TT, TT,
        Gpart, nullptr, 0, 128, nullptr,nullptr,nullptr,nullptr,nullptr);
    k_gsum<<<dim3(10, BB), blk, 66048>>>(Gpart, Gh, Gl);
    // H = Wq G (G symmetric -> NT; 3 products) -> Hh,Hl
    k_wmma_nt<0,3,0,0><<<dim3(CC/128, CC/128, BB), blk, 81920>>>(
        wqh, wql, (size_t)0, Gh, Gl, (size_t)CC*CC, CC, CC, CC,
        Hh, Hl, (size_t)CC*CC, CC, nullptr,nullptr,nullptr,nullptr,nullptr);
    // dots = H Wk^T + rank-1, scaled (3 products)
    k_wmma_nt<1,3,0,0><<<dim3(CC/128, CC/128, BB), blk, 81920>>>(
        Hh, Hl, (size_t)CC*CC, wkh, wkl, (size_t)0, CC, CC, CC,
        dots, nullptr, (size_t)CC*CC, CC, u, w, bq, bk, nullptr);
    // softmax -> ah ; r = attn.bv
    k_softmax<<<dim3(CC/8, BB), blk>>>(dots, ah, bv, rr);
    // M = ah WvT^T (1 product), fp16-hi out
    k_wmma_nt<4,1,0,0><<<dim3(CC/128, CC/128, BB), blk, 40960>>>(
        ah, nullptr, (size_t)CC*CC, wvth, nullptr, (size_t)0, CC, CC, CC,
        Mh, nullptr, (size_t)CC*CC, CC, nullptr,nullptr,nullptr,nullptr,nullptr);
    // out = Mh xh + r  (NN, single product)
    k_wmma_nt<2,1,0,1><<<dim3(TT/128, CC/128, BB), blk, 37888>>>(
        Mh, nullptr, (size_t)CC*CC, xh, nullptr, (size_t)CC*TT, 512, CC, TT,
        out, nullptr, (size_t)CC*TT, TT, nullptr,nullptr,nullptr,nullptr, rr);
}